// round 3
// baseline (speedup 1.0000x reference)
#include <cuda_runtime.h>
#include <cstdint>

#define HF 128
#define LSEQ 2048
#define BATCH 128
#define CHUNK 512
#define ELEMS 8

// ---------- packed f32x2 helpers (Blackwell 2x fp32) ----------
__device__ __forceinline__ unsigned long long pk2(float lo, float hi) {
    unsigned long long r;
    asm("mov.b64 %0, {%1, %2};" : "=l"(r) : "f"(lo), "f"(hi));
    return r;
}
__device__ __forceinline__ unsigned long long ffma2(unsigned long long a,
                                                    unsigned long long b,
                                                    unsigned long long c) {
    unsigned long long d;
    asm("fma.rn.f32x2 %0, %1, %2, %3;" : "=l"(d) : "l"(a), "l"(b), "l"(c));
    return d;
}
__device__ __forceinline__ float2 unpk2(unsigned long long a) {
    float x, y;
    asm("mov.b64 {%0, %1}, %2;" : "=f"(x), "=f"(y) : "l"(a));
    return make_float2(x, y);
}

__global__ void zero_out_kernel(float* out) { out[threadIdx.x] = 0.f; }

// TYPE 0: bond length MLP  (G=1 geo scalar, D=33)
// TYPE 1: angle MLP        (G=1, D=49)
// TYPE 2: dihedral MLP     (G=2, D=66)
template <int TYPE, int D, int G>
__device__ __forceinline__ void run_mlp(
        const float* __restrict__ R, const int* __restrict__ seq,
        const float* __restrict__ emb,
        const float* __restrict__ W1, const float* __restrict__ b1,
        const float* __restrict__ W2, const float* __restrict__ b2,
        const float* __restrict__ W3, const float* __restrict__ b3,
        float* __restrict__ out) {
    constexpr int N   = LSEQ - 1 - TYPE;     // elements per batch
    constexpr int Dp  = (D + 3) & ~3;        // pad feature dim to x4
    constexpr int Dp4 = Dp / 4;
    constexpr int Dp2 = Dp / 2;

    __shared__ float  s_emb[20 * 16];
    __shared__ int    s_seq[CHUNK + 4];
    __shared__ float  s_geo[CHUNK * G];
    __shared__ float4 s_x4[ELEMS * Dp4];
    __shared__ float4 s_h14[ELEMS * (HF / 4)];
    __shared__ float  s_red[4];

    float* s_x  = (float*)s_x4;
    float* s_h1 = (float*)s_h14;

    const int tid    = threadIdx.x;
    const int j      = tid;          // output column owned by this thread
    const int lane   = tid & 31;
    const int warp   = tid >> 5;
    const int b      = blockIdx.y;
    const int cstart = blockIdx.x * CHUNK;

    // ---- embedding table to smem ----
    for (int t = tid; t < 20 * 16; t += 128) s_emb[t] = emb[t];
    // ---- seq slice (with slack for +k lookahead) ----
    for (int t = tid; t < CHUNK + 4; t += 128) {
        int idx = cstart + t;
        if (idx >= LSEQ) idx = LSEQ - 1;
        s_seq[t] = seq[b * LSEQ + idx];
    }
    // ---- per-column scalars ----
    const float b1j = b1[j];
    const float b2j = b2[j];
    const float w3j = W3[j];
    const float b3s = b3[0];
    // ---- W1 column j -> registers as packed k-pairs (zero padded) ----
    unsigned long long w1p[Dp2];
    #pragma unroll
    for (int p = 0; p < Dp2; p++) {
        float lo = (2 * p + 0 < D) ? __ldg(&W1[(2 * p + 0) * HF + j]) : 0.f;
        float hi = (2 * p + 1 < D) ? __ldg(&W1[(2 * p + 1) * HF + j]) : 0.f;
        w1p[p] = pk2(lo, hi);
    }
    // ---- W2 column j -> registers as packed k-pairs ----
    unsigned long long w2p[64];
    #pragma unroll
    for (int p = 0; p < 64; p++) {
        float lo = __ldg(&W2[(2 * p + 0) * HF + j]);
        float hi = __ldg(&W2[(2 * p + 1) * HF + j]);
        w2p[p] = pk2(lo, hi);
    }
    // ---- geometry scalars for the whole chunk (fully parallel) ----
    const float* Rb = R + (size_t)b * LSEQ * 3;
    for (int t = tid; t < CHUNK; t += 128) {
        int i = cstart + t;
        if (i < N) {
            if (TYPE == 0) {
                float dx = __ldg(&Rb[(i + 1) * 3 + 0]) - __ldg(&Rb[i * 3 + 0]);
                float dy = __ldg(&Rb[(i + 1) * 3 + 1]) - __ldg(&Rb[i * 3 + 1]);
                float dz = __ldg(&Rb[(i + 1) * 3 + 2]) - __ldg(&Rb[i * 3 + 2]);
                s_geo[t] = sqrtf(dx * dx + dy * dy + dz * dz);
            } else if (TYPE == 1) {
                float ax = __ldg(&Rb[i * 3 + 0]), ay = __ldg(&Rb[i * 3 + 1]), az = __ldg(&Rb[i * 3 + 2]);
                float bx = __ldg(&Rb[(i + 1) * 3 + 0]), by = __ldg(&Rb[(i + 1) * 3 + 1]), bz = __ldg(&Rb[(i + 1) * 3 + 2]);
                float cx = __ldg(&Rb[(i + 2) * 3 + 0]), cy = __ldg(&Rb[(i + 2) * 3 + 1]), cz = __ldg(&Rb[(i + 2) * 3 + 2]);
                float ux = ax - bx, uy = ay - by, uz = az - bz;  // -d[i]
                float vx = cx - bx, vy = cy - by, vz = cz - bz;  //  d[i+1]
                float num = ux * vx + uy * vy + uz * vz;
                float den = sqrtf((ux * ux + uy * uy + uz * uz) * (vx * vx + vy * vy + vz * vz));
                float c = num / den;
                s_geo[t] = fminf(1.f, fmaxf(-1.f, c));
            } else {
                float p0x = __ldg(&Rb[i * 3 + 0]), p0y = __ldg(&Rb[i * 3 + 1]), p0z = __ldg(&Rb[i * 3 + 2]);
                float p1x = __ldg(&Rb[(i + 1) * 3 + 0]), p1y = __ldg(&Rb[(i + 1) * 3 + 1]), p1z = __ldg(&Rb[(i + 1) * 3 + 2]);
                float p2x = __ldg(&Rb[(i + 2) * 3 + 0]), p2y = __ldg(&Rb[(i + 2) * 3 + 1]), p2z = __ldg(&Rb[(i + 2) * 3 + 2]);
                float p3x = __ldg(&Rb[(i + 3) * 3 + 0]), p3y = __ldg(&Rb[(i + 3) * 3 + 1]), p3z = __ldg(&Rb[(i + 3) * 3 + 2]);
                float b1x = p1x - p0x, b1y = p1y - p0y, b1z = p1z - p0z;
                float b2x = p2x - p1x, b2y = p2y - p1y, b2z = p2z - p1z;
                float b3x = p3x - p2x, b3y = p3y - p2y, b3z = p3z - p2z;
                float n1x = b1y * b2z - b1z * b2y, n1y = b1z * b2x - b1x * b2z, n1z = b1x * b2y - b1y * b2x;
                float n2x = b2y * b3z - b2z * b3y, n2y = b2z * b3x - b2x * b3z, n2z = b2x * b3y - b2y * b3x;
                float inv = rsqrtf(b2x * b2x + b2y * b2y + b2z * b2z);
                float ux = b2x * inv, uy = b2y * inv, uz = b2z * inv;
                float m1x = n1y * uz - n1z * uy, m1y = n1z * ux - n1x * uz, m1z = n1x * uy - n1y * ux;
                float yv = m1x * n2x + m1y * n2y + m1z * n2z;  // sin numerator
                float xv = n1x * n2x + n1y * n2y + n1z * n2z;  // cos numerator
                float rn = rsqrtf(xv * xv + yv * yv);
                s_geo[t * 2 + 0] = yv * rn;
                s_geo[t * 2 + 1] = xv * rn;
            }
        } else {
            if (G == 1) s_geo[t] = 0.f;
            else { s_geo[t * 2 + 0] = 0.f; s_geo[t * 2 + 1] = 0.f; }
        }
    }
    __syncthreads();

    float thread_sum = 0.f;

    for (int g0 = 0; g0 < CHUNK; g0 += ELEMS) {
        // ---- cooperative feature assembly: x[e][0:Dp] ----
        for (int t = tid; t < ELEMS * Dp; t += 128) {
            int e = t / Dp;
            int v = t - e * Dp;
            int li = g0 + e;
            int gi = cstart + li;
            float val = 0.f;
            if (gi < N && v < D) {
                if (v < G) {
                    val = s_geo[li * G + v];
                } else {
                    int k = (v - G) >> 4;
                    int c = (v - G) & 15;
                    val = s_emb[s_seq[li + k] * 16 + c];
                }
            }
            s_x[t] = val;
        }
        __syncthreads();

        // ---- layer 1: h1[e][j] = relu(b1[j] + x . W1[:,j]) (W1 col in regs) ----
        unsigned long long a1[ELEMS];
        #pragma unroll
        for (int e = 0; e < ELEMS; e++) a1[e] = pk2(b1j, 0.f);
        #pragma unroll
        for (int i4 = 0; i4 < Dp4; i4++) {
            #pragma unroll
            for (int e = 0; e < ELEMS; e++) {
                float4 xq = s_x4[e * Dp4 + i4];
                a1[e] = ffma2(pk2(xq.x, xq.y), w1p[2 * i4 + 0], a1[e]);
                a1[e] = ffma2(pk2(xq.z, xq.w), w1p[2 * i4 + 1], a1[e]);
            }
        }
        #pragma unroll
        for (int e = 0; e < ELEMS; e++) {
            float2 u = unpk2(a1[e]);
            s_h1[e * HF + j] = fmaxf(u.x + u.y, 0.f);
        }
        __syncthreads();

        // ---- layer 2 + 3: thread_sum += relu(b2 + h1.W2[:,j]) * W3[j] ----
        unsigned long long a2[ELEMS];
        #pragma unroll
        for (int e = 0; e < ELEMS; e++) a2[e] = pk2(b2j, 0.f);
        #pragma unroll
        for (int i4 = 0; i4 < HF / 4; i4++) {
            #pragma unroll
            for (int e = 0; e < ELEMS; e++) {
                float4 hq = s_h14[e * (HF / 4) + i4];
                a2[e] = ffma2(pk2(hq.x, hq.y), w2p[2 * i4 + 0], a2[e]);
                a2[e] = ffma2(pk2(hq.z, hq.w), w2p[2 * i4 + 1], a2[e]);
            }
        }
        #pragma unroll
        for (int e = 0; e < ELEMS; e++) {
            float2 u = unpk2(a2[e]);
            float v = fmaxf(u.x + u.y, 0.f) * w3j;
            bool valid = (cstart + g0 + e) < N;
            thread_sum += valid ? v : 0.f;
        }
        // next iteration's s_x writes are safe: all reads of s_x done before
        // the h1 barrier; next h1 writes are fenced by the next x barrier.
    }

    // ---- one block reduction at the end ----
    #pragma unroll
    for (int off = 16; off; off >>= 1)
        thread_sum += __shfl_xor_sync(0xffffffffu, thread_sum, off);
    if (lane == 0) s_red[warp] = thread_sum;
    __syncthreads();
    if (tid == 0) {
        int count = N - cstart;
        if (count > CHUNK) count = CHUNK;
        float total = s_red[0] + s_red[1] + s_red[2] + s_red[3] + (float)count * b3s;
        atomicAdd(&out[b], total);
    }
}

__global__ __launch_bounds__(128, 2)
void fused_energy_kernel(const float* __restrict__ R, const int* __restrict__ seq,
                         const float* __restrict__ emb,
                         const float* fl_W1, const float* fl_b1, const float* fl_W2,
                         const float* fl_b2, const float* fl_W3, const float* fl_b3,
                         const float* ft_W1, const float* ft_b1, const float* ft_W2,
                         const float* ft_b2, const float* ft_W3, const float* ft_b3,
                         const float* fp_W1, const float* fp_b1, const float* fp_W2,
                         const float* fp_b2, const float* fp_W3, const float* fp_b3,
                         float* __restrict__ out) {
    if (blockIdx.z == 0) {
        run_mlp<0, 33, 1>(R, seq, emb, fl_W1, fl_b1, fl_W2, fl_b2, fl_W3, fl_b3, out);
    } else if (blockIdx.z == 1) {
        run_mlp<1, 49, 1>(R, seq, emb, ft_W1, ft_b1, ft_W2, ft_b2, ft_W3, ft_b3, out);
    } else {
        run_mlp<2, 66, 2>(R, seq, emb, fp_W1, fp_b1, fp_W2, fp_b2, fp_W3, fp_b3, out);
    }
}

extern "C" void kernel_launch(void* const* d_in, const int* in_sizes, int n_in,
                              void* d_out, int out_size) {
    const float* R   = (const float*)d_in[0];
    const int*   seq = (const int*)d_in[1];
    const float* emb = (const float*)d_in[2];
    const float* fl_W1 = (const float*)d_in[3];
    const float* fl_b1 = (const float*)d_in[4];
    const float* fl_W2 = (const float*)d_in[5];
    const float* fl_b2 = (const float*)d_in[6];
    const float* fl_W3 = (const float*)d_in[7];
    const float* fl_b3 = (const float*)d_in[8];
    const float* ft_W1 = (const float*)d_in[9];
    const float* ft_b1 = (const float*)d_in[10];
    const float* ft_W2 = (const float*)d_in[11];
    const float* ft_b2 = (const float*)d_in[12];
    const float* ft_W3 = (const float*)d_in[13];
    const float* ft_b3 = (const float*)d_in[14];
    const float* fp_W1 = (const float*)d_in[15];
    const float* fp_b1 = (const float*)d_in[16];
    const float* fp_W2 = (const float*)d_in[17];
    const float* fp_b2 = (const float*)d_in[18];
    const float* fp_W3 = (const float*)d_in[19];
    const float* fp_b3 = (const float*)d_in[20];
    float* out = (float*)d_out;

    zero_out_kernel<<<1, 128>>>(out);

    dim3 grid(LSEQ / CHUNK, BATCH, 3);  // 4 x 128 x 3
    fused_energy_kernel<<<grid, 128>>>(R, seq, emb,
        fl_W1, fl_b1, fl_W2, fl_b2, fl_W3, fl_b3,
        ft_W1, ft_b1, ft_W2, ft_b2, ft_W3, ft_b3,
        fp_W1, fp_b1, fp_W2, fp_b2, fp_W3, fp_b3, out);
}

// round 4
// speedup vs baseline: 1.3636x; 1.3636x over previous
#include <cuda_runtime.h>
#include <cstdint>

#define HF 128
#define LSEQ 2048
#define BATCH 128
#define CHUNK 512
#define ELEMS 8

// ---------- packed f32x2 helpers (Blackwell 2x fp32) ----------
__device__ __forceinline__ unsigned long long pk2(float lo, float hi) {
    unsigned long long r;
    asm("mov.b64 %0, {%1, %2};" : "=l"(r) : "f"(lo), "f"(hi));
    return r;
}
__device__ __forceinline__ unsigned long long ffma2(unsigned long long a,
                                                    unsigned long long b,
                                                    unsigned long long c) {
    unsigned long long d;
    asm("fma.rn.f32x2 %0, %1, %2, %3;" : "=l"(d) : "l"(a), "l"(b), "l"(c));
    return d;
}
__device__ __forceinline__ float2 unpk2(unsigned long long a) {
    float x, y;
    asm("mov.b64 {%0, %1}, %2;" : "=f"(x), "=f"(y) : "l"(a));
    return make_float2(x, y);
}

__global__ void zero_out_kernel(float* out) { out[threadIdx.x] = 0.f; }

// Precomputed P tables: P[gk][aa][j] = emb[aa] . W1_block(gk rows 16)
// gk 0..1 -> type0 (G=1), gk 2..4 -> type1 (G=1), gk 5..8 -> type2 (G=2)
__device__ float g_P[9 * 20 * HF];

__global__ void precompute_P_kernel(const float* __restrict__ emb,
                                    const float* __restrict__ W1_0,
                                    const float* __restrict__ W1_1,
                                    const float* __restrict__ W1_2) {
    int aa = blockIdx.x;
    int gk = blockIdx.y;
    int j  = threadIdx.x;
    const float* W1;
    int k, G;
    if (gk < 2)      { W1 = W1_0; k = gk;     G = 1; }
    else if (gk < 5) { W1 = W1_1; k = gk - 2; G = 1; }
    else             { W1 = W1_2; k = gk - 5; G = 2; }
    float s = 0.f;
    #pragma unroll
    for (int c = 0; c < 16; c++)
        s += emb[aa * 16 + c] * W1[(G + k * 16 + c) * HF + j];
    g_P[(gk * 20 + aa) * HF + j] = s;
}

// shared buffer layout (max over types, type2): P 40960 + seq 2080 + geo 4096
// + h1 4096 + red 16
#define SBUF_BYTES (40960 + 2080 + 4096 + 4096 + 16)

// TYPE 0: bond length (G=1, NE=2)  TYPE 1: angle (G=1, NE=3)  TYPE 2: dihedral (G=2, NE=4)
template <int TYPE, int G, int NE>
__device__ __forceinline__ void run_mlp(
        char* __restrict__ sbuf,
        const float* __restrict__ R, const int* __restrict__ seq,
        const float* __restrict__ Pg,
        const float* __restrict__ W1, const float* __restrict__ b1,
        const float* __restrict__ W2, const float* __restrict__ b2,
        const float* __restrict__ W3, const float* __restrict__ b3,
        float* __restrict__ out) {
    constexpr int N = LSEQ - 1 - TYPE;       // elements per batch
    constexpr int P_FLOATS = NE * 20 * HF;

    float* s_P   = (float*)sbuf;
    int*   s_seq = (int*)(sbuf + P_FLOATS * 4);
    float* s_geo = (float*)(sbuf + P_FLOATS * 4 + 2080);
    float* s_h1  = (float*)(sbuf + P_FLOATS * 4 + 2080 + CHUNK * G * 4);
    float* s_red = s_h1 + ELEMS * HF;
    float4* s_h14 = (float4*)s_h1;

    const int tid    = threadIdx.x;
    const int j      = tid;          // output column owned by this thread
    const int lane   = tid & 31;
    const int warp   = tid >> 5;
    const int b      = blockIdx.y;
    const int cstart = blockIdx.x * CHUNK;

    // ---- P tables -> smem ----
    for (int t = tid; t < P_FLOATS; t += 128) s_P[t] = Pg[t];
    // ---- seq slice (with slack for +k lookahead) ----
    for (int t = tid; t < CHUNK + 4; t += 128) {
        int idx = cstart + t;
        if (idx >= LSEQ) idx = LSEQ - 1;
        s_seq[t] = seq[b * LSEQ + idx];
    }
    // ---- per-column scalars ----
    const float b1j = b1[j];
    const float b2j = b2[j];
    const float w3j = W3[j];
    const float b3s = b3[0];
    const float w1g0 = W1[0 * HF + j];
    const float w1g1 = (G == 2) ? W1[1 * HF + j] : 0.f;
    // ---- W2 column j -> registers as packed k-pairs ----
    unsigned long long w2p[64];
    #pragma unroll
    for (int p = 0; p < 64; p++) {
        float lo = __ldg(&W2[(2 * p + 0) * HF + j]);
        float hi = __ldg(&W2[(2 * p + 1) * HF + j]);
        w2p[p] = pk2(lo, hi);
    }
    // ---- geometry scalars for the whole chunk (fully parallel) ----
    const float* Rb = R + (size_t)b * LSEQ * 3;
    for (int t = tid; t < CHUNK; t += 128) {
        int i = cstart + t;
        if (i < N) {
            if (TYPE == 0) {
                float dx = __ldg(&Rb[(i + 1) * 3 + 0]) - __ldg(&Rb[i * 3 + 0]);
                float dy = __ldg(&Rb[(i + 1) * 3 + 1]) - __ldg(&Rb[i * 3 + 1]);
                float dz = __ldg(&Rb[(i + 1) * 3 + 2]) - __ldg(&Rb[i * 3 + 2]);
                s_geo[t] = sqrtf(dx * dx + dy * dy + dz * dz);
            } else if (TYPE == 1) {
                float ax = __ldg(&Rb[i * 3 + 0]), ay = __ldg(&Rb[i * 3 + 1]), az = __ldg(&Rb[i * 3 + 2]);
                float bx = __ldg(&Rb[(i + 1) * 3 + 0]), by = __ldg(&Rb[(i + 1) * 3 + 1]), bz = __ldg(&Rb[(i + 1) * 3 + 2]);
                float cx = __ldg(&Rb[(i + 2) * 3 + 0]), cy = __ldg(&Rb[(i + 2) * 3 + 1]), cz = __ldg(&Rb[(i + 2) * 3 + 2]);
                float ux = ax - bx, uy = ay - by, uz = az - bz;
                float vx = cx - bx, vy = cy - by, vz = cz - bz;
                float num = ux * vx + uy * vy + uz * vz;
                float den = sqrtf((ux * ux + uy * uy + uz * uz) * (vx * vx + vy * vy + vz * vz));
                float c = num / den;
                s_geo[t] = fminf(1.f, fmaxf(-1.f, c));
            } else {
                float p0x = __ldg(&Rb[i * 3 + 0]), p0y = __ldg(&Rb[i * 3 + 1]), p0z = __ldg(&Rb[i * 3 + 2]);
                float p1x = __ldg(&Rb[(i + 1) * 3 + 0]), p1y = __ldg(&Rb[(i + 1) * 3 + 1]), p1z = __ldg(&Rb[(i + 1) * 3 + 2]);
                float p2x = __ldg(&Rb[(i + 2) * 3 + 0]), p2y = __ldg(&Rb[(i + 2) * 3 + 1]), p2z = __ldg(&Rb[(i + 2) * 3 + 2]);
                float p3x = __ldg(&Rb[(i + 3) * 3 + 0]), p3y = __ldg(&Rb[(i + 3) * 3 + 1]), p3z = __ldg(&Rb[(i + 3) * 3 + 2]);
                float b1x = p1x - p0x, b1y = p1y - p0y, b1z = p1z - p0z;
                float b2x = p2x - p1x, b2y = p2y - p1y, b2z = p2z - p1z;
                float b3x = p3x - p2x, b3y = p3y - p2y, b3z = p3z - p2z;
                float n1x = b1y * b2z - b1z * b2y, n1y = b1z * b2x - b1x * b2z, n1z = b1x * b2y - b1y * b2x;
                float n2x = b2y * b3z - b2z * b3y, n2y = b2z * b3x - b2x * b3z, n2z = b2x * b3y - b2y * b3x;
                float inv = rsqrtf(b2x * b2x + b2y * b2y + b2z * b2z);
                float ux = b2x * inv, uy = b2y * inv, uz = b2z * inv;
                float m1x = n1y * uz - n1z * uy, m1y = n1z * ux - n1x * uz, m1z = n1x * uy - n1y * ux;
                float yv = m1x * n2x + m1y * n2y + m1z * n2z;  // sin numerator
                float xv = n1x * n2x + n1y * n2y + n1z * n2z;  // cos numerator
                float rn = rsqrtf(xv * xv + yv * yv);
                s_geo[t * 2 + 0] = yv * rn;
                s_geo[t * 2 + 1] = xv * rn;
            }
        } else {
            if (G == 1) s_geo[t] = 0.f;
            else { s_geo[t * 2 + 0] = 0.f; s_geo[t * 2 + 1] = 0.f; }
        }
    }
    __syncthreads();

    float thread_sum = 0.f;

    for (int g0 = 0; g0 < CHUNK; g0 += ELEMS) {
        // ---- layer 1 via P tables: h1[e][j] = relu(b1 + geo.w1g + sum_k P_k[aa]) ----
        #pragma unroll
        for (int e = 0; e < ELEMS; e++) {
            int li = g0 + e;
            float acc = b1j;
            if (G == 2) {
                float2 sc = ((const float2*)s_geo)[li];
                acc = fmaf(sc.x, w1g0, acc);
                acc = fmaf(sc.y, w1g1, acc);
            } else {
                acc = fmaf(s_geo[li], w1g0, acc);
            }
            #pragma unroll
            for (int k = 0; k < NE; k++)
                acc += s_P[(k * 20 + s_seq[li + k]) * HF + j];
            s_h1[e * HF + j] = fmaxf(acc, 0.f);
        }
        __syncthreads();

        // ---- layer 2 + 3: thread_sum += relu(b2 + h1.W2[:,j]) * W3[j] ----
        unsigned long long a2[ELEMS];
        #pragma unroll
        for (int e = 0; e < ELEMS; e++) a2[e] = pk2(b2j, 0.f);
        #pragma unroll
        for (int i4 = 0; i4 < HF / 4; i4++) {
            #pragma unroll
            for (int e = 0; e < ELEMS; e++) {
                float4 hq = s_h14[e * (HF / 4) + i4];
                a2[e] = ffma2(pk2(hq.x, hq.y), w2p[2 * i4 + 0], a2[e]);
                a2[e] = ffma2(pk2(hq.z, hq.w), w2p[2 * i4 + 1], a2[e]);
            }
        }
        #pragma unroll
        for (int e = 0; e < ELEMS; e++) {
            float2 u = unpk2(a2[e]);
            float v = fmaxf(u.x + u.y, 0.f) * w3j;
            bool valid = (cstart + g0 + e) < N;
            thread_sum += valid ? v : 0.f;
        }
        __syncthreads();  // fence before next group's h1 writes
    }

    // ---- one block reduction at the end ----
    #pragma unroll
    for (int off = 16; off; off >>= 1)
        thread_sum += __shfl_xor_sync(0xffffffffu, thread_sum, off);
    if (lane == 0) s_red[warp] = thread_sum;
    __syncthreads();
    if (tid == 0) {
        int count = N - cstart;
        if (count > CHUNK) count = CHUNK;
        float total = s_red[0] + s_red[1] + s_red[2] + s_red[3] + (float)count * b3s;
        atomicAdd(&out[b], total);
    }
}

__global__ __launch_bounds__(128, 2)
void fused_energy_kernel(const float* __restrict__ R, const int* __restrict__ seq,
                         const float* fl_W1, const float* fl_b1, const float* fl_W2,
                         const float* fl_b2, const float* fl_W3, const float* fl_b3,
                         const float* ft_W1, const float* ft_b1, const float* ft_W2,
                         const float* ft_b2, const float* ft_W3, const float* ft_b3,
                         const float* fp_W1, const float* fp_b1, const float* fp_W2,
                         const float* fp_b2, const float* fp_W3, const float* fp_b3,
                         float* __restrict__ out) {
    __shared__ __align__(16) char sbuf[SBUF_BYTES];
    if (blockIdx.z == 0) {
        run_mlp<0, 1, 2>(sbuf, R, seq, g_P + 0 * 20 * HF,
                         fl_W1, fl_b1, fl_W2, fl_b2, fl_W3, fl_b3, out);
    } else if (blockIdx.z == 1) {
        run_mlp<1, 1, 3>(sbuf, R, seq, g_P + 2 * 20 * HF,
                         ft_W1, ft_b1, ft_W2, ft_b2, ft_W3, ft_b3, out);
    } else {
        run_mlp<2, 2, 4>(sbuf, R, seq, g_P + 5 * 20 * HF,
                         fp_W1, fp_b1, fp_W2, fp_b2, fp_W3, fp_b3, out);
    }
}

extern "C" void kernel_launch(void* const* d_in, const int* in_sizes, int n_in,
                              void* d_out, int out_size) {
    const float* R   = (const float*)d_in[0];
    const int*   seq = (const int*)d_in[1];
    const float* emb = (const float*)d_in[2];
    const float* fl_W1 = (const float*)d_in[3];
    const float* fl_b1 = (const float*)d_in[4];
    const float* fl_W2 = (const float*)d_in[5];
    const float* fl_b2 = (const float*)d_in[6];
    const float* fl_W3 = (const float*)d_in[7];
    const float* fl_b3 = (const float*)d_in[8];
    const float* ft_W1 = (const float*)d_in[9];
    const float* ft_b1 = (const float*)d_in[10];
    const float* ft_W2 = (const float*)d_in[11];
    const float* ft_b2 = (const float*)d_in[12];
    const float* ft_W3 = (const float*)d_in[13];
    const float* ft_b3 = (const float*)d_in[14];
    const float* fp_W1 = (const float*)d_in[15];
    const float* fp_b1 = (const float*)d_in[16];
    const float* fp_W2 = (const float*)d_in[17];
    const float* fp_b2 = (const float*)d_in[18];
    const float* fp_W3 = (const float*)d_in[19];
    const float* fp_b3 = (const float*)d_in[20];
    float* out = (float*)d_out;

    zero_out_kernel<<<1, 128>>>(out);

    dim3 pgrid(20, 9);
    precompute_P_kernel<<<pgrid, 128>>>(emb, fl_W1, ft_W1, fp_W1);

    dim3 grid(LSEQ / CHUNK, BATCH, 3);  // 4 x 128 x 3
    fused_energy_kernel<<<grid, 128>>>(R, seq,
        fl_W1, fl_b1, fl_W2, fl_b2, fl_W3, fl_b3,
        ft_W1, ft_b1, ft_W2, ft_b2, ft_W3, ft_b3,
        fp_W1, fp_b1, fp_W2, fp_b2, fp_W3, fp_b3, out);
}

// round 9
// speedup vs baseline: 3.2052x; 2.3506x over previous
#include <cuda_runtime.h>
#include <cuda_bf16.h>
#include <cstdint>

#define HF 128
#define LSEQ 2048
#define BATCH 128
#define CHUNK 512
#define NTILES 4
#define THREADS 256

#define ASTRIDE 136   // A row stride in bf16 (272B = 17*16B -> ldmatrix conflict-free)
#define BSTRIDE 68    // packed-B row stride in words ((4g+tig)%32 distinct -> conflict-free)

// smem byte offsets
#define SM_P    0
#define SM_BLO  40960
#define SM_AHI  75776
#define SM_ALO  110592
#define SM_GEO  145408
#define SM_SEQ  149504
#define SM_RED  151584
#define SM_TOTAL 151680

// ---------------- helpers ----------------
__device__ __forceinline__ uint32_t smem_u32(const void* p) {
    uint32_t a;
    asm("{ .reg .u64 t; cvta.to.shared.u64 t, %1; cvt.u32.u64 %0, t; }" : "=r"(a) : "l"(p));
    return a;
}
__device__ __forceinline__ void ldmatrix4(uint32_t a[4], uint32_t addr) {
    asm volatile("ldmatrix.sync.aligned.m8n8.x4.shared.b16 {%0,%1,%2,%3}, [%4];"
                 : "=r"(a[0]), "=r"(a[1]), "=r"(a[2]), "=r"(a[3]) : "r"(addr));
}
__device__ __forceinline__ void mma_bf16(float c[4], const uint32_t a[4],
                                         uint32_t b0, uint32_t b1) {
    asm volatile("mma.sync.aligned.m16n8k16.row.col.f32.bf16.bf16.f32 "
                 "{%0,%1,%2,%3}, {%4,%5,%6,%7}, {%8,%9}, {%0,%1,%2,%3};"
                 : "+f"(c[0]), "+f"(c[1]), "+f"(c[2]), "+f"(c[3])
                 : "r"(a[0]), "r"(a[1]), "r"(a[2]), "r"(a[3]), "r"(b0), "r"(b1));
}

// ---------------- globals ----------------
__device__ float g_P[9 * 20 * HF];
__device__ uint32_t g_Bhi_pk[3][128 * BSTRIDE];   // packed bf16x2 frag images
__device__ uint32_t g_Blo_pk[3][128 * BSTRIDE];

__global__ void zero_out_kernel(float* out) { out[threadIdx.x] = 0.f; }

__global__ void precompute_P_kernel(const float* __restrict__ emb,
                                    const float* __restrict__ W1_0,
                                    const float* __restrict__ W1_1,
                                    const float* __restrict__ W1_2) {
    int aa = blockIdx.x, gk = blockIdx.y, j = threadIdx.x;
    const float* W1; int k, G;
    if (gk < 2)      { W1 = W1_0; k = gk;     G = 1; }
    else if (gk < 5) { W1 = W1_1; k = gk - 2; G = 1; }
    else             { W1 = W1_2; k = gk - 5; G = 2; }
    float s = 0.f;
    #pragma unroll
    for (int c = 0; c < 16; c++)
        s += emb[aa * 16 + c] * W1[(G + k * 16 + c) * HF + j];
    g_P[(gk * 20 + aa) * HF + j] = s;
}

// pack W2 into per-fragment bf16x2 images: pk[n*68 + kp] = {W2[2kp][n], W2[2kp+1][n]}
__global__ void precompute_Bpk_kernel(const float* __restrict__ W2_0,
                                      const float* __restrict__ W2_1,
                                      const float* __restrict__ W2_2) {
    int n = blockIdx.x, type = blockIdx.y, kp = threadIdx.x;  // kp 0..63
    const float* W2 = (type == 0) ? W2_0 : (type == 1) ? W2_1 : W2_2;
    float w0 = W2[(2 * kp + 0) * HF + n];
    float w1 = W2[(2 * kp + 1) * HF + n];
    __nv_bfloat16 h0 = __float2bfloat16(w0), h1 = __float2bfloat16(w1);
    __nv_bfloat16 l0 = __float2bfloat16(w0 - __bfloat162float(h0));
    __nv_bfloat16 l1 = __float2bfloat16(w1 - __bfloat162float(h1));
    g_Bhi_pk[type][n * BSTRIDE + kp] =
        (uint32_t)__bfloat16_as_ushort(h0) | ((uint32_t)__bfloat16_as_ushort(h1) << 16);
    g_Blo_pk[type][n * BSTRIDE + kp] =
        (uint32_t)__bfloat16_as_ushort(l0) | ((uint32_t)__bfloat16_as_ushort(l1) << 16);
}

// ---------------- main fused kernel ----------------
template <int TYPE, int G, int NE>
__device__ __forceinline__ void run_type(
        char* sm, uint32_t smb,
        const float* __restrict__ R, const int* __restrict__ seq,
        const float* __restrict__ Pg,
        const float* __restrict__ W1, const float* __restrict__ b1,
        const float* __restrict__ b2, const float* __restrict__ W3,
        const float* __restrict__ b3,
        const uint32_t* __restrict__ Bhi_g, const uint32_t* __restrict__ Blo_g,
        float* __restrict__ out) {
    constexpr int Nelem = LSEQ - 1 - TYPE;
    constexpr int P_FLOATS = NE * 20 * HF;

    float* s_P   = (float*)(sm + SM_P);
    int*   s_seq = (int*)(sm + SM_SEQ);
    float* s_geo = (float*)(sm + SM_GEO);
    float* s_red = (float*)(sm + SM_RED);
    __nv_bfloat16* s_Ahi = (__nv_bfloat16*)(sm + SM_AHI);
    __nv_bfloat16* s_Alo = (__nv_bfloat16*)(sm + SM_ALO);
    const uint32_t* s_Blo = (const uint32_t*)(sm + SM_BLO);

    const int tid  = threadIdx.x;
    const int lane = tid & 31;
    const int wid  = tid >> 5;
    const int jcol = tid & 127;
    const int half = tid >> 7;
    const int mw   = wid >> 2;       // 0..1 : M-half of warp grid
    const int nw   = wid & 3;        // 0..3 : N-quarter
    const int gid  = lane >> 2;      // 0..7
    const int tig  = lane & 3;       // 0..3
    const int b    = blockIdx.y;
    const int cstart = blockIdx.x * CHUNK;

    // ---- bulk copies: Blo image -> smem, Bhi image -> staging (in s_Ahi) ----
    {
        const uint4* sb = (const uint4*)Blo_g;
        uint4* db = (uint4*)(sm + SM_BLO);
        const uint4* sh = (const uint4*)Bhi_g;
        uint4* dh = (uint4*)(sm + SM_AHI);
        for (int t = tid; t < 128 * BSTRIDE / 4; t += THREADS) {
            db[t] = sb[t];
            dh[t] = sh[t];
        }
    }
    for (int t = tid; t < P_FLOATS; t += THREADS) s_P[t] = Pg[t];
    for (int t = tid; t < CHUNK + 4; t += THREADS) {
        int idx = cstart + t;
        if (idx >= LSEQ) idx = LSEQ - 1;
        s_seq[t] = seq[b * LSEQ + idx];
    }
    const float b1j  = b1[jcol];
    const float w1g0 = W1[jcol];
    const float w1g1 = (G == 2) ? W1[HF + jcol] : 0.f;
    const float b3s  = b3[0];

    // per-thread epilogue coefficients for its 8 columns
    float b2v[8], w3v[8];
    #pragma unroll
    for (int nt = 0; nt < 4; nt++) {
        #pragma unroll
        for (int u = 0; u < 2; u++) {
            int c = nw * 32 + nt * 8 + tig * 2 + u;
            b2v[nt * 2 + u] = __ldg(&b2[c]);
            w3v[nt * 2 + u] = __ldg(&W3[c]);
        }
    }

    // ---- geometry for the whole 512-elem chunk ----
    const float* Rb = R + (size_t)b * LSEQ * 3;
    for (int t = tid; t < CHUNK; t += THREADS) {
        int i = cstart + t;
        if (i < Nelem) {
            if (TYPE == 0) {
                float dx = __ldg(&Rb[(i + 1) * 3 + 0]) - __ldg(&Rb[i * 3 + 0]);
                float dy = __ldg(&Rb[(i + 1) * 3 + 1]) - __ldg(&Rb[i * 3 + 1]);
                float dz = __ldg(&Rb[(i + 1) * 3 + 2]) - __ldg(&Rb[i * 3 + 2]);
                s_geo[t] = sqrtf(dx * dx + dy * dy + dz * dz);
            } else if (TYPE == 1) {
                float ax = __ldg(&Rb[i * 3 + 0]), ay = __ldg(&Rb[i * 3 + 1]), az = __ldg(&Rb[i * 3 + 2]);
                float bx = __ldg(&Rb[(i + 1) * 3 + 0]), by = __ldg(&Rb[(i + 1) * 3 + 1]), bz = __ldg(&Rb[(i + 1) * 3 + 2]);
                float cx = __ldg(&Rb[(i + 2) * 3 + 0]), cy = __ldg(&Rb[(i + 2) * 3 + 1]), cz = __ldg(&Rb[(i + 2) * 3 + 2]);
                float ux = ax - bx, uy = ay - by, uz = az - bz;
                float vx = cx - bx, vy = cy - by, vz = cz - bz;
                float num = ux * vx + uy * vy + uz * vz;
                float den = sqrtf((ux * ux + uy * uy + uz * uz) * (vx * vx + vy * vy + vz * vz));
                float c = num / den;
                s_geo[t] = fminf(1.f, fmaxf(-1.f, c));
            } else {
                float p0x = __ldg(&Rb[i * 3 + 0]), p0y = __ldg(&Rb[i * 3 + 1]), p0z = __ldg(&Rb[i * 3 + 2]);
                float p1x = __ldg(&Rb[(i + 1) * 3 + 0]), p1y = __ldg(&Rb[(i + 1) * 3 + 1]), p1z = __ldg(&Rb[(i + 1) * 3 + 2]);
                float p2x = __ldg(&Rb[(i + 2) * 3 + 0]), p2y = __ldg(&Rb[(i + 2) * 3 + 1]), p2z = __ldg(&Rb[(i + 2) * 3 + 2]);
                float p3x = __ldg(&Rb[(i + 3) * 3 + 0]), p3y = __ldg(&Rb[(i + 3) * 3 + 1]), p3z = __ldg(&Rb[(i + 3) * 3 + 2]);
                float b1x = p1x - p0x, b1y = p1y - p0y, b1z = p1z - p0z;
                float b2x = p2x - p1x, b2y = p2y - p1y, b2z = p2z - p1z;
                float b3x = p3x - p2x, b3y = p3y - p2y, b3z = p3z - p2z;
                float n1x = b1y * b2z - b1z * b2y, n1y = b1z * b2x - b1x * b2z, n1z = b1x * b2y - b1y * b2x;
                float n2x = b2y * b3z - b2z * b3y, n2y = b2z * b3x - b2x * b3z, n2z = b2x * b3y - b2y * b3x;
                float inv = rsqrtf(b2x * b2x + b2y * b2y + b2z * b2z);
                float ux = b2x * inv, uy = b2y * inv, uz = b2z * inv;
                float m1x = n1y * uz - n1z * uy, m1y = n1z * ux - n1x * uz, m1z = n1x * uy - n1y * ux;
                float yv = m1x * n2x + m1y * n2y + m1z * n2z;
                float xv = n1x * n2x + n1y * n2y + n1z * n2z;
                float rn = rsqrtf(xv * xv + yv * yv);
                s_geo[t * 2 + 0] = yv * rn;
                s_geo[t * 2 + 1] = xv * rn;
            }
        } else {
            if (G == 1) s_geo[t] = 0.f;
            else { s_geo[t * 2 + 0] = 0.f; s_geo[t * 2 + 1] = 0.f; }
        }
    }
    __syncthreads();

    // ---- load Bhi fragments from staging into registers ----
    uint32_t bhi0[4][8], bhi1[4][8];
    {
        const uint32_t* st = (const uint32_t*)(sm + SM_AHI);
        #pragma unroll
        for (int nt = 0; nt < 4; nt++) {
            int n = nw * 32 + nt * 8 + gid;
            #pragma unroll
            for (int kt = 0; kt < 8; kt++) {
                bhi0[nt][kt] = st[n * BSTRIDE + kt * 8 + tig];
                bhi1[nt][kt] = st[n * BSTRIDE + kt * 8 + tig + 4];
            }
        }
    }
    __syncthreads();   // staging (s_Ahi) now reusable

    // ldmatrix per-thread base address into A (row = lane&15, col-block = lane>>4)
    const uint32_t a_off = (uint32_t)((mw * 64 + (lane & 15)) * ASTRIDE + (lane >> 4) * 8) * 2;
    const uint32_t ahi_base = smb + SM_AHI + a_off;
    const uint32_t alo_base = smb + SM_ALO + a_off;

    float thread_sum = 0.f;

    for (int tile = 0; tile < NTILES; tile++) {
        const int tstart = tile * 128;

        // ---- layer 1: thread (jcol) computes h1 for 64 elems, writes bf16 hi/lo ----
        {
            const int li0 = tstart + half * 64;
            int sq[NE];
            #pragma unroll
            for (int k = 0; k < NE; k++) sq[k] = s_seq[li0 + k];
            for (int e = 0; e < 64; e++) {
                const int li = li0 + e;
                float acc = b1j;
                if (G == 2) {
                    float2 sc = ((const float2*)s_geo)[li];
                    acc = fmaf(sc.x, w1g0, fmaf(sc.y, w1g1, acc));
                } else {
                    acc = fmaf(s_geo[li], w1g0, acc);
                }
                #pragma unroll
                for (int k = 0; k < NE; k++)
                    acc += s_P[(k * 20 + sq[k]) * HF + jcol];
                #pragma unroll
                for (int k = 0; k < NE - 1; k++) sq[k] = sq[k + 1];
                sq[NE - 1] = s_seq[li + NE];
                float h = fmaxf(acc, 0.f);
                __nv_bfloat16 hb = __float2bfloat16(h);
                float lf = h - __bfloat162float(hb);
                int row = half * 64 + e;
                s_Ahi[row * ASTRIDE + jcol] = hb;
                s_Alo[row * ASTRIDE + jcol] = __float2bfloat16(lf);
            }
        }
        __syncthreads();

        // ---- MMA: C = Ahi*Bhi + Ahi*Blo + Alo*Bhi ----
        float c[4][4][4];
        #pragma unroll
        for (int mt = 0; mt < 4; mt++)
            #pragma unroll
            for (int nt = 0; nt < 4; nt++)
                #pragma unroll
                for (int q = 0; q < 4; q++) c[mt][nt][q] = 0.f;

        #pragma unroll
        for (int kt = 0; kt < 8; kt++) {
            uint32_t bl0[4], bl1[4];
            #pragma unroll
            for (int nt = 0; nt < 4; nt++) {
                int n = nw * 32 + nt * 8 + gid;
                bl0[nt] = s_Blo[n * BSTRIDE + kt * 8 + tig];
                bl1[nt] = s_Blo[n * BSTRIDE + kt * 8 + tig + 4];
            }
            #pragma unroll
            for (int mt = 0; mt < 4; mt++) {
                uint32_t a[4];
                ldmatrix4(a, ahi_base + (uint32_t)(mt * 16 * ASTRIDE * 2 + kt * 32));
                #pragma unroll
                for (int nt = 0; nt < 4; nt++) {
                    mma_bf16(c[mt][nt], a, bhi0[nt][kt], bhi1[nt][kt]);
                    mma_bf16(c[mt][nt], a, bl0[nt], bl1[nt]);
                }
            }
        }
        #pragma unroll
        for (int kt = 0; kt < 8; kt++) {
            #pragma unroll
            for (int mt = 0; mt < 4; mt++) {
                uint32_t a[4];
                ldmatrix4(a, alo_base + (uint32_t)(mt * 16 * ASTRIDE * 2 + kt * 32));
                #pragma unroll
                for (int nt = 0; nt < 4; nt++)
                    mma_bf16(c[mt][nt], a, bhi0[nt][kt], bhi1[nt][kt]);
            }
        }

        // ---- epilogue: sum relu(D + b2)*w3 over valid rows ----
        {
            const int e0 = cstart + tstart + mw * 64;
            #pragma unroll
            for (int mt = 0; mt < 4; mt++) {
                const int r0 = mt * 16 + gid;
                const bool v0 = (e0 + r0) < Nelem;
                const bool v1 = (e0 + r0 + 8) < Nelem;
                float p0 = 0.f, p1 = 0.f;
                #pragma unroll
                for (int nt = 0; nt < 4; nt++) {
                    p0 += fmaxf(c[mt][nt][0] + b2v[nt * 2 + 0], 0.f) * w3v[nt * 2 + 0]
                        + fmaxf(c[mt][nt][1] + b2v[nt * 2 + 1], 0.f) * w3v[nt * 2 + 1];
                    p1 += fmaxf(c[mt][nt][2] + b2v[nt * 2 + 0], 0.f) * w3v[nt * 2 + 0]
                        + fmaxf(c[mt][nt][3] + b2v[nt * 2 + 1], 0.f) * w3v[nt * 2 + 1];
                }
                thread_sum += (v0 ? p0 : 0.f) + (v1 ? p1 : 0.f);
            }
        }
        __syncthreads();   // A buffers reused by next tile
    }

    // ---- final reduction ----
    #pragma unroll
    for (int off = 16; off; off >>= 1)
        thread_sum += __shfl_xor_sync(0xffffffffu, thread_sum, off);
    if (lane == 0) s_red[wid] = thread_sum;
    __syncthreads();
    if (tid == 0) {
        int count = Nelem - cstart;
        if (count > CHUNK) count = CHUNK;
        float total = 0.f;
        #pragma unroll
        for (int w = 0; w < 8; w++) total += s_red[w];
        atomicAdd(&out[b], total + (float)count * b3s);
    }
}

__global__ __launch_bounds__(THREADS, 1)
void fused_energy_kernel(const float* __restrict__ R, const int* __restrict__ seq,
                         const float* fl_W1, const float* fl_b1, const float* fl_b2,
                         const float* fl_W3, const float* fl_b3,
                         const float* ft_W1, const float* ft_b1, const float* ft_b2,
                         const float* ft_W3, const float* ft_b3,
                         const float* fp_W1, const float* fp_b1, const float* fp_b2,
                         const float* fp_W3, const float* fp_b3,
                         float* __restrict__ out) {
    extern __shared__ char sm[];
    uint32_t smb = smem_u32(sm);
    if (blockIdx.z == 0) {
        run_type<0, 1, 2>(sm, smb, R, seq, g_P + 0 * 20 * HF,
                          fl_W1, fl_b1, fl_b2, fl_W3, fl_b3,
                          g_Bhi_pk[0], g_Blo_pk[0], out);
    } else if (blockIdx.z == 1) {
        run_type<1, 1, 3>(sm, smb, R, seq, g_P + 2 * 20 * HF,
                          ft_W1, ft_b1, ft_b2, ft_W3, ft_b3,
                          g_Bhi_pk[1], g_Blo_pk[1], out);
    } else {
        run_type<2, 2, 4>(sm, smb, R, seq, g_P + 5 * 20 * HF,
                          fp_W1, fp_b1, fp_b2, fp_W3, fp_b3,
                          g_Bhi_pk[2], g_Blo_pk[2], out);
    }
}

extern "C" void kernel_launch(void* const* d_in, const int* in_sizes, int n_in,
                              void* d_out, int out_size) {
    const float* R   = (const float*)d_in[0];
    const int*   seq = (const int*)d_in[1];
    const float* emb = (const float*)d_in[2];
    const float* fl_W1 = (const float*)d_in[3];
    const float* fl_b1 = (const float*)d_in[4];
    const float* fl_W2 = (const float*)d_in[5];
    const float* fl_b2 = (const float*)d_in[6];
    const float* fl_W3 = (const float*)d_in[7];
    const float* fl_b3 = (const float*)d_in[8];
    const float* ft_W1 = (const float*)d_in[9];
    const float* ft_b1 = (const float*)d_in[10];
    const float* ft_W2 = (const float*)d_in[11];
    const float* ft_b2 = (const float*)d_in[12];
    const float* ft_W3 = (const float*)d_in[13];
    const float* ft_b3 = (const float*)d_in[14];
    const float* fp_W1 = (const float*)d_in[15];
    const float* fp_b1 = (const float*)d_in[16];
    const float* fp_W2 = (const float*)d_in[17];
    const float* fp_b2 = (const float*)d_in[18];
    const float* fp_W3 = (const float*)d_in[19];
    const float* fp_b3 = (const float*)d_in[20];
    float* out = (float*)d_out;

    cudaFuncSetAttribute(fused_energy_kernel,
                         cudaFuncAttributeMaxDynamicSharedMemorySize, SM_TOTAL);

    zero_out_kernel<<<1, 128>>>(out);

    dim3 pgrid(20, 9);
    precompute_P_kernel<<<pgrid, 128>>>(emb, fl_W1, ft_W1, fp_W1);
    dim3 bgrid(128, 3);
    precompute_Bpk_kernel<<<bgrid, 64>>>(fl_W2, ft_W2, fp_W2);

    dim3 grid(LSEQ / CHUNK, BATCH, 3);  // 4 x 128 x 3
    fused_energy_kernel<<<grid, THREADS, SM_TOTAL>>>(R, seq,
        fl_W1, fl_b1, fl_b2, fl_W3, fl_b3,
        ft_W1, ft_b1, ft_b2, ft_W3, ft_b3,
        fp_W1, fp_b1, fp_b2, fp_W3, fp_b3, out);
}

// round 10
// speedup vs baseline: 3.3362x; 1.0409x over previous
#include <cuda_runtime.h>
#include <cuda_bf16.h>
#include <cstdint>

#define HF 128
#define LSEQ 2048
#define BATCH 128
#define CHUNK 512
#define TILE_M 64
#define NTILES (CHUNK / TILE_M)
#define THREADS 256

#define ASTRIDE 136   // A row stride in bf16 (272B -> ldmatrix conflict-free)
#define BSTRIDE 68    // packed-B row stride in words ((4g+tig)%32 distinct)

// smem byte offsets
#define SM_BHI  0
#define SM_BLO  34816
#define SM_AHI  69632
#define SM_ALO  87040
#define SM_GEO  104448
#define SM_SEQ  108544
#define SM_RED  110624
#define SM_TOTAL 110688

// ---------------- helpers ----------------
__device__ __forceinline__ uint32_t smem_u32(const void* p) {
    uint32_t a;
    asm("{ .reg .u64 t; cvta.to.shared.u64 t, %1; cvt.u32.u64 %0, t; }" : "=r"(a) : "l"(p));
    return a;
}
__device__ __forceinline__ void ldmatrix4(uint32_t a[4], uint32_t addr) {
    asm volatile("ldmatrix.sync.aligned.m8n8.x4.shared.b16 {%0,%1,%2,%3}, [%4];"
                 : "=r"(a[0]), "=r"(a[1]), "=r"(a[2]), "=r"(a[3]) : "r"(addr));
}
__device__ __forceinline__ void mma_bf16(float c[4], const uint32_t a[4],
                                         uint32_t b0, uint32_t b1) {
    asm volatile("mma.sync.aligned.m16n8k16.row.col.f32.bf16.bf16.f32 "
                 "{%0,%1,%2,%3}, {%4,%5,%6,%7}, {%8,%9}, {%0,%1,%2,%3};"
                 : "+f"(c[0]), "+f"(c[1]), "+f"(c[2]), "+f"(c[3])
                 : "r"(a[0]), "r"(a[1]), "r"(a[2]), "r"(a[3]), "r"(b0), "r"(b1));
}

// ---------------- globals ----------------
__device__ float g_P[9 * 20 * HF];
__device__ uint32_t g_Bhi_pk[3][128 * BSTRIDE];
__device__ uint32_t g_Blo_pk[3][128 * BSTRIDE];

__global__ void zero_out_kernel(float* out) { out[threadIdx.x] = 0.f; }

__global__ void precompute_P_kernel(const float* __restrict__ emb,
                                    const float* __restrict__ W1_0,
                                    const float* __restrict__ W1_1,
                                    const float* __restrict__ W1_2) {
    int aa = blockIdx.x, gk = blockIdx.y, j = threadIdx.x;
    const float* W1; int k, G;
    if (gk < 2)      { W1 = W1_0; k = gk;     G = 1; }
    else if (gk < 5) { W1 = W1_1; k = gk - 2; G = 1; }
    else             { W1 = W1_2; k = gk - 5; G = 2; }
    float s = 0.f;
    #pragma unroll
    for (int c = 0; c < 16; c++)
        s += emb[aa * 16 + c] * W1[(G + k * 16 + c) * HF + j];
    g_P[(gk * 20 + aa) * HF + j] = s;
}

__global__ void precompute_Bpk_kernel(const float* __restrict__ W2_0,
                                      const float* __restrict__ W2_1,
                                      const float* __restrict__ W2_2) {
    int n = blockIdx.x, type = blockIdx.y, kp = threadIdx.x;  // kp 0..63
    const float* W2 = (type == 0) ? W2_0 : (type == 1) ? W2_1 : W2_2;
    float w0 = W2[(2 * kp + 0) * HF + n];
    float w1 = W2[(2 * kp + 1) * HF + n];
    __nv_bfloat16 h0 = __float2bfloat16(w0), h1 = __float2bfloat16(w1);
    __nv_bfloat16 l0 = __float2bfloat16(w0 - __bfloat162float(h0));
    __nv_bfloat16 l1 = __float2bfloat16(w1 - __bfloat162float(h1));
    g_Bhi_pk[type][n * BSTRIDE + kp] =
        (uint32_t)__bfloat16_as_ushort(h0) | ((uint32_t)__bfloat16_as_ushort(h1) << 16);
    g_Blo_pk[type][n * BSTRIDE + kp] =
        (uint32_t)__bfloat16_as_ushort(l0) | ((uint32_t)__bfloat16_as_ushort(l1) << 16);
}

// ---------------- main fused kernel ----------------
template <int TYPE, int G, int NE>
__device__ __forceinline__ void run_type(
        char* sm, uint32_t smb,
        const float* __restrict__ R, const int* __restrict__ seq,
        const float* __restrict__ Pg,
        const float* __restrict__ W1, const float* __restrict__ b1,
        const float* __restrict__ b2, const float* __restrict__ W3,
        const float* __restrict__ b3,
        const uint32_t* __restrict__ Bhi_g, const uint32_t* __restrict__ Blo_g,
        float* __restrict__ out) {
    constexpr int Nelem = LSEQ - 1 - TYPE;

    int*   s_seq = (int*)(sm + SM_SEQ);
    float* s_geo = (float*)(sm + SM_GEO);
    float* s_red = (float*)(sm + SM_RED);
    __nv_bfloat16* s_Ahi = (__nv_bfloat16*)(sm + SM_AHI);
    __nv_bfloat16* s_Alo = (__nv_bfloat16*)(sm + SM_ALO);
    const uint32_t* s_Bhi = (const uint32_t*)(sm + SM_BHI);
    const uint32_t* s_Blo = (const uint32_t*)(sm + SM_BLO);

    const int tid  = threadIdx.x;
    const int lane = tid & 31;
    const int wid  = tid >> 5;
    const int jcol = tid & 127;
    const int half = tid >> 7;
    const int mw   = wid >> 2;       // 0..1 : M-half (32 rows each)
    const int nw   = wid & 3;        // 0..3 : N-quarter
    const int gid  = lane >> 2;      // 0..7
    const int tig  = lane & 3;       // 0..3
    const int b    = blockIdx.y;
    const int cstart = blockIdx.x * CHUNK;

    // ---- bulk copies: B images -> smem ----
    {
        const uint4* sh = (const uint4*)Bhi_g;
        const uint4* sb = (const uint4*)Blo_g;
        uint4* dh = (uint4*)(sm + SM_BHI);
        uint4* db = (uint4*)(sm + SM_BLO);
        for (int t = tid; t < 128 * BSTRIDE / 4; t += THREADS) {
            dh[t] = sh[t];
            db[t] = sb[t];
        }
    }
    for (int t = tid; t < CHUNK + 4; t += THREADS) {
        int idx = cstart + t;
        if (idx >= LSEQ) idx = LSEQ - 1;
        s_seq[t] = seq[b * LSEQ + idx];
    }
    const float b1j  = b1[jcol];
    const float w1g0 = W1[jcol];
    const float w1g1 = (G == 2) ? W1[HF + jcol] : 0.f;
    const float b3s  = b3[0];

    // per-thread epilogue coefficients for its 8 columns
    float b2v[8], w3v[8];
    #pragma unroll
    for (int nt = 0; nt < 4; nt++) {
        #pragma unroll
        for (int u = 0; u < 2; u++) {
            int c = nw * 32 + nt * 8 + tig * 2 + u;
            b2v[nt * 2 + u] = __ldg(&b2[c]);
            w3v[nt * 2 + u] = __ldg(&W3[c]);
        }
    }

    // ---- geometry for the whole 512-elem chunk ----
    const float* Rb = R + (size_t)b * LSEQ * 3;
    for (int t = tid; t < CHUNK; t += THREADS) {
        int i = cstart + t;
        if (i < Nelem) {
            if (TYPE == 0) {
                float dx = __ldg(&Rb[(i + 1) * 3 + 0]) - __ldg(&Rb[i * 3 + 0]);
                float dy = __ldg(&Rb[(i + 1) * 3 + 1]) - __ldg(&Rb[i * 3 + 1]);
                float dz = __ldg(&Rb[(i + 1) * 3 + 2]) - __ldg(&Rb[i * 3 + 2]);
                s_geo[t] = sqrtf(dx * dx + dy * dy + dz * dz);
            } else if (TYPE == 1) {
                float ax = __ldg(&Rb[i * 3 + 0]), ay = __ldg(&Rb[i * 3 + 1]), az = __ldg(&Rb[i * 3 + 2]);
                float bx = __ldg(&Rb[(i + 1) * 3 + 0]), by = __ldg(&Rb[(i + 1) * 3 + 1]), bz = __ldg(&Rb[(i + 1) * 3 + 2]);
                float cx = __ldg(&Rb[(i + 2) * 3 + 0]), cy = __ldg(&Rb[(i + 2) * 3 + 1]), cz = __ldg(&Rb[(i + 2) * 3 + 2]);
                float ux = ax - bx, uy = ay - by, uz = az - bz;
                float vx = cx - bx, vy = cy - by, vz = cz - bz;
                float num = ux * vx + uy * vy + uz * vz;
                float den = sqrtf((ux * ux + uy * uy + uz * uz) * (vx * vx + vy * vy + vz * vz));
                float c = num / den;
                s_geo[t] = fminf(1.f, fmaxf(-1.f, c));
            } else {
                float p0x = __ldg(&Rb[i * 3 + 0]), p0y = __ldg(&Rb[i * 3 + 1]), p0z = __ldg(&Rb[i * 3 + 2]);
                float p1x = __ldg(&Rb[(i + 1) * 3 + 0]), p1y = __ldg(&Rb[(i + 1) * 3 + 1]), p1z = __ldg(&Rb[(i + 1) * 3 + 2]);
                float p2x = __ldg(&Rb[(i + 2) * 3 + 0]), p2y = __ldg(&Rb[(i + 2) * 3 + 1]), p2z = __ldg(&Rb[(i + 2) * 3 + 2]);
                float p3x = __ldg(&Rb[(i + 3) * 3 + 0]), p3y = __ldg(&Rb[(i + 3) * 3 + 1]), p3z = __ldg(&Rb[(i + 3) * 3 + 2]);
                float b1x = p1x - p0x, b1y = p1y - p0y, b1z = p1z - p0z;
                float b2x = p2x - p1x, b2y = p2y - p1y, b2z = p2z - p1z;
                float b3x = p3x - p2x, b3y = p3y - p2y, b3z = p3z - p2z;
                float n1x = b1y * b2z - b1z * b2y, n1y = b1z * b2x - b1x * b2z, n1z = b1x * b2y - b1y * b2x;
                float n2x = b2y * b3z - b2z * b3y, n2y = b2z * b3x - b2x * b3z, n2z = b2x * b3y - b2y * b3x;
                float inv = rsqrtf(b2x * b2x + b2y * b2y + b2z * b2z);
                float ux = b2x * inv, uy = b2y * inv, uz = b2z * inv;
                float m1x = n1y * uz - n1z * uy, m1y = n1z * ux - n1x * uz, m1z = n1x * uy - n1y * ux;
                float yv = m1x * n2x + m1y * n2y + m1z * n2z;
                float xv = n1x * n2x + n1y * n2y + n1z * n2z;
                float rn = rsqrtf(xv * xv + yv * yv);
                s_geo[t * 2 + 0] = yv * rn;
                s_geo[t * 2 + 1] = xv * rn;
            }
        } else {
            if (G == 1) s_geo[t] = 0.f;
            else { s_geo[t * 2 + 0] = 0.f; s_geo[t * 2 + 1] = 0.f; }
        }
    }
    __syncthreads();

    // ldmatrix per-thread base address into A (row = lane&15, col-block = lane>>4)
    const uint32_t a_off = (uint32_t)((mw * 32 + (lane & 15)) * ASTRIDE + (lane >> 4) * 8) * 2;
    const uint32_t ahi_base = smb + SM_AHI + a_off;
    const uint32_t alo_base = smb + SM_ALO + a_off;

    float thread_sum = 0.f;

    for (int tile = 0; tile < NTILES; tile++) {
        const int tstart = tile * TILE_M;

        // ---- layer 1: thread (jcol, half) computes h1 for 32 rows ----
        {
            const int li0 = tstart + half * 32;
            int sq[NE];
            #pragma unroll
            for (int k = 0; k < NE; k++) sq[k] = s_seq[li0 + k];
            #pragma unroll 4
            for (int e = 0; e < 32; e++) {
                const int li = li0 + e;
                float acc = b1j;
                if (G == 2) {
                    float2 sc = ((const float2*)s_geo)[li];
                    acc = fmaf(sc.x, w1g0, fmaf(sc.y, w1g1, acc));
                } else {
                    acc = fmaf(s_geo[li], w1g0, acc);
                }
                #pragma unroll
                for (int k = 0; k < NE; k++)
                    acc += __ldg(&Pg[(k * 20 + sq[k]) * HF + jcol]);
                #pragma unroll
                for (int k = 0; k < NE - 1; k++) sq[k] = sq[k + 1];
                sq[NE - 1] = s_seq[li + NE];
                float h = fmaxf(acc, 0.f);
                __nv_bfloat16 hb = __float2bfloat16(h);
                float lf = h - __bfloat162float(hb);
                int row = half * 32 + e;
                s_Ahi[row * ASTRIDE + jcol] = hb;
                s_Alo[row * ASTRIDE + jcol] = __float2bfloat16(lf);
            }
        }
        __syncthreads();

        // ---- MMA: C = Ahi*Bhi + Ahi*Blo + Alo*Bhi ----
        float c[2][4][4];
        #pragma unroll
        for (int mt = 0; mt < 2; mt++)
            #pragma unroll
            for (int nt = 0; nt < 4; nt++)
                #pragma unroll
                for (int q = 0; q < 4; q++) c[mt][nt][q] = 0.f;

        #pragma unroll
        for (int kt = 0; kt < 8; kt++) {
            uint32_t bh0[4], bh1[4], bl0[4], bl1[4];
            #pragma unroll
            for (int nt = 0; nt < 4; nt++) {
                int n = nw * 32 + nt * 8 + gid;
                bh0[nt] = s_Bhi[n * BSTRIDE + kt * 8 + tig];
                bh1[nt] = s_Bhi[n * BSTRIDE + kt * 8 + tig + 4];
                bl0[nt] = s_Blo[n * BSTRIDE + kt * 8 + tig];
                bl1[nt] = s_Blo[n * BSTRIDE + kt * 8 + tig + 4];
            }
            #pragma unroll
            for (int mt = 0; mt < 2; mt++) {
                uint32_t ah[4], al[4];
                ldmatrix4(ah, ahi_base + (uint32_t)(mt * 16 * ASTRIDE * 2 + kt * 32));
                ldmatrix4(al, alo_base + (uint32_t)(mt * 16 * ASTRIDE * 2 + kt * 32));
                #pragma unroll
                for (int nt = 0; nt < 4; nt++) {
                    mma_bf16(c[mt][nt], ah, bh0[nt], bh1[nt]);
                    mma_bf16(c[mt][nt], ah, bl0[nt], bl1[nt]);
                    mma_bf16(c[mt][nt], al, bh0[nt], bh1[nt]);
                }
            }
        }

        // ---- epilogue: sum relu(D + b2)*w3 over valid rows ----
        {
            const int e0 = cstart + tstart + mw * 32;
            #pragma unroll
            for (int mt = 0; mt < 2; mt++) {
                const int r0 = mt * 16 + gid;
                const bool v0 = (e0 + r0) < Nelem;
                const bool v1 = (e0 + r0 + 8) < Nelem;
                float p0 = 0.f, p1 = 0.f;
                #pragma unroll
                for (int nt = 0; nt < 4; nt++) {
                    p0 += fmaxf(c[mt][nt][0] + b2v[nt * 2 + 0], 0.f) * w3v[nt * 2 + 0]
                        + fmaxf(c[mt][nt][1] + b2v[nt * 2 + 1], 0.f) * w3v[nt * 2 + 1];
                    p1 += fmaxf(c[mt][nt][2] + b2v[nt * 2 + 0], 0.f) * w3v[nt * 2 + 0]
                        + fmaxf(c[mt][nt][3] + b2v[nt * 2 + 1], 0.f) * w3v[nt * 2 + 1];
                }
                thread_sum += (v0 ? p0 : 0.f) + (v1 ? p1 : 0.f);
            }
        }
        __syncthreads();   // A buffers reused by next tile
    }

    // ---- final reduction ----
    #pragma unroll
    for (int off = 16; off; off >>= 1)
        thread_sum += __shfl_xor_sync(0xffffffffu, thread_sum, off);
    if (lane == 0) s_red[wid] = thread_sum;
    __syncthreads();
    if (tid == 0) {
        int count = Nelem - cstart;
        if (count > CHUNK) count = CHUNK;
        float total = 0.f;
        #pragma unroll
        for (int w = 0; w < 8; w++) total += s_red[w];
        atomicAdd(&out[b], total + (float)count * b3s);
    }
}

__global__ __launch_bounds__(THREADS, 2)
void fused_energy_kernel(const float* __restrict__ R, const int* __restrict__ seq,
                         const float* fl_W1, const float* fl_b1, const float* fl_b2,
                         const float* fl_W3, const float* fl_b3,
                         const float* ft_W1, const float* ft_b1, const float* ft_b2,
                         const float* ft_W3, const float* ft_b3,
                         const float* fp_W1, const float* fp_b1, const float* fp_b2,
                         const float* fp_W3, const float* fp_b3,
                         float* __restrict__ out) {
    extern __shared__ char sm[];
    uint32_t smb = smem_u32(sm);
    if (blockIdx.z == 0) {
        run_type<0, 1, 2>(sm, smb, R, seq, g_P + 0 * 20 * HF,
                          fl_W1, fl_b1, fl_b2, fl_W3, fl_b3,
                          g_Bhi_pk[0], g_Blo_pk[0], out);
    } else if (blockIdx.z == 1) {
        run_type<1, 1, 3>(sm, smb, R, seq, g_P + 2 * 20 * HF,
                          ft_W1, ft_b1, ft_b2, ft_W3, ft_b3,
                          g_Bhi_pk[1], g_Blo_pk[1], out);
    } else {
        run_type<2, 2, 4>(sm, smb, R, seq, g_P + 5 * 20 * HF,
                          fp_W1, fp_b1, fp_b2, fp_W3, fp_b3,
                          g_Bhi_pk[2], g_Blo_pk[2], out);
    }
}

extern "C" void kernel_launch(void* const* d_in, const int* in_sizes, int n_in,
                              void* d_out, int out_size) {
    const float* R   = (const float*)d_in[0];
    const int*   seq = (const int*)d_in[1];
    const float* emb = (const float*)d_in[2];
    const float* fl_W1 = (const float*)d_in[3];
    const float* fl_b1 = (const float*)d_in[4];
    const float* fl_W2 = (const float*)d_in[5];
    const float* fl_b2 = (const float*)d_in[6];
    const float* fl_W3 = (const float*)d_in[7];
    const float* fl_b3 = (const float*)d_in[8];
    const float* ft_W1 = (const float*)d_in[9];
    const float* ft_b1 = (const float*)d_in[10];
    const float* ft_W2 = (const float*)d_in[11];
    const float* ft_b2 = (const float*)d_in[12];
    const float* ft_W3 = (const float*)d_in[13];
    const float* ft_b3 = (const float*)d_in[14];
    const float* fp_W1 = (const float*)d_in[15];
    const float* fp_b1 = (const float*)d_in[16];
    const float* fp_W2 = (const float*)d_in[17];
    const float* fp_b2 = (const float*)d_in[18];
    const float* fp_W3 = (const float*)d_in[19];
    const float* fp_b3 = (const float*)d_in[20];
    float* out = (float*)d_out;

    cudaFuncSetAttribute(fused_energy_kernel,
                         cudaFuncAttributeMaxDynamicSharedMemorySize, SM_TOTAL);

    zero_out_kernel<<<1, 128>>>(out);

    dim3 pgrid(20, 9);
    precompute_P_kernel<<<pgrid, 128>>>(emb, fl_W1, ft_W1, fp_W1);
    dim3 bgrid(128, 3);
    precompute_Bpk_kernel<<<bgrid, 64>>>(fl_W2, ft_W2, fp_W2);

    dim3 grid(LSEQ / CHUNK, BATCH, 3);  // 4 x 128 x 3
    fused_energy_kernel<<<grid, THREADS, SM_TOTAL>>>(R, seq,
        fl_W1, fl_b1, fl_b2, fl_W3, fl_b3,
        ft_W1, ft_b1, ft_b2, ft_W3, ft_b3,
        fp_W1, fp_b1, fp_b2, fp_W3, fp_b3, out);
}